// round 7
// baseline (speedup 1.0000x reference)
#include <cuda_runtime.h>
#include <math.h>

// Problem constants
#define SEQ   2048
#define DIM   4096
#define NH    32
#define NKV   8
#define HD    128
#define KVDIM (NKV * HD)   // 1024

// -------- scratch (device globals; no runtime allocation allowed) --------
__device__ float g_Q[SEQ * DIM];       // [2048][32][128]  (RoPE'd, pre-scaled)
__device__ float g_K[SEQ * KVDIM];     // [2048][8][128]   (RoPE'd)
__device__ float g_V[SEQ * KVDIM];     // [2048][8][128]
__device__ float g_attn[SEQ * DIM];    // attention output [2048][4096]

// ============================================================================
// fp32 SIMT GEMM: C[M,N] = A[M,K] @ B[K,N], all row-major.
// 128x128 block tile, BK=16, 256 threads, 8x8 register tile per thread.
// M % 128 == 0, N % 128 == 0, K % 16 == 0 (all true for this problem).
// ============================================================================
__global__ __launch_bounds__(256) void gemm_f32(
    const float* __restrict__ A, const float* __restrict__ B,
    float* __restrict__ C, int M, int N, int K)
{
    __shared__ float As[16][132];   // stored transposed: As[k][m]; 132 pad -> fewer store conflicts
    __shared__ float Bs[16][132];   // Bs[k][n]

    const int tid = threadIdx.x;
    const int tx  = tid & 15;       // 0..15 (output columns)
    const int ty  = tid >> 4;       // 0..15 (output rows)
    const int rowBase = blockIdx.y * 128;
    const int colBase = blockIdx.x * 128;

    float acc[8][8];
    #pragma unroll
    for (int i = 0; i < 8; i++)
        #pragma unroll
        for (int j = 0; j < 8; j++) acc[i][j] = 0.f;

    // A loader: 2 x float4 per thread (128 rows x 16 k)
    const int aRow = tid >> 2;            // 0..63
    const int aCol = (tid & 3) << 2;      // 0,4,8,12
    // B loader: 2 x float4 per thread (16 rows x 128 n)
    const int bRow = tid >> 5;            // 0..7
    const int bCol = (tid & 31) << 2;     // 0..124

    const float* Aptr = A + (size_t)(rowBase + aRow) * K + aCol;
    const float* Bptr = B + (size_t)bRow * N + colBase + bCol;

    for (int k0 = 0; k0 < K; k0 += 16) {
        #pragma unroll
        for (int p = 0; p < 2; p++) {
            float4 v = *(const float4*)(Aptr + (size_t)p * 64 * K + k0);
            int r = aRow + p * 64;
            As[aCol + 0][r] = v.x;
            As[aCol + 1][r] = v.y;
            As[aCol + 2][r] = v.z;
            As[aCol + 3][r] = v.w;
        }
        #pragma unroll
        for (int p = 0; p < 2; p++) {
            *(float4*)&Bs[bRow + p * 8][bCol] =
                *(const float4*)(Bptr + (size_t)(k0 + p * 8) * N);
        }
        __syncthreads();

        #pragma unroll
        for (int kk = 0; kk < 16; kk++) {
            // rows: ty*8 .. ty*8+7 (broadcast reads)
            float4 a0 = *(float4*)&As[kk][ty * 8];
            float4 a1 = *(float4*)&As[kk][ty * 8 + 4];
            // cols split tx*4 and 64+tx*4 -> conflict-free vectorized LDS
            float4 b0 = *(float4*)&Bs[kk][tx * 4];
            float4 b1 = *(float4*)&Bs[kk][64 + tx * 4];
            float ra[8] = {a0.x, a0.y, a0.z, a0.w, a1.x, a1.y, a1.z, a1.w};
            float rb[8] = {b0.x, b0.y, b0.z, b0.w, b1.x, b1.y, b1.z, b1.w};
            #pragma unroll
            for (int i = 0; i < 8; i++)
                #pragma unroll
                for (int j = 0; j < 8; j++)
                    acc[i][j] += ra[i] * rb[j];
        }
        __syncthreads();
    }

    #pragma unroll
    for (int i = 0; i < 8; i++) {
        float* crow = C + (size_t)(rowBase + ty * 8 + i) * N + colBase;
        *(float4*)(crow + tx * 4) =
            make_float4(acc[i][0], acc[i][1], acc[i][2], acc[i][3]);
        *(float4*)(crow + 64 + tx * 4) =
            make_float4(acc[i][4], acc[i][5], acc[i][6], acc[i][7]);
    }
}

// ============================================================================
// RoPE (interleaved pairs, matches reference), optional scale folded in.
// t: [SEQ][n_heads][128], one thread per (pos, head, pair).
// ============================================================================
__global__ void rope_kernel(float* __restrict__ t, int n_heads, float scale)
{
    int idx = blockIdx.x * blockDim.x + threadIdx.x;
    int total = SEQ * n_heads * (HD / 2);
    if (idx >= total) return;
    int i   = idx & 63;                 // pair index 0..63
    int h   = (idx >> 6) % n_heads;
    int pos = idx / (64 * n_heads);

    float inv = powf(10000.0f, -(float)(2 * i) / 128.0f);  // accurate powf
    float ang = (float)pos * inv;
    float s, c;
    sincosf(ang, &s, &c);

    float* p = t + ((size_t)pos * n_heads + h) * HD + 2 * i;
    float a = p[0], b = p[1];
    p[0] = (a * c - b * s) * scale;
    p[1] = (a * s + b * c) * scale;
}

// ============================================================================
// Flash-style causal GQA attention, fp32.
// grid = (SEQ/64 q-blocks, NH heads), 256 threads (16x16).
// smem: Qs[64][128], Kst[128][64] (transposed), Vs[64][128], Ps[64][68].
// Thread (ty,tx): score sub-tile rows 4*ty..+3 x cols 4*tx..+3;
// output rows 4*ty..+3 x dims {tx*4..+3, 64+tx*4..+3}.
// ============================================================================
#define PS 68   // padded Ps row stride (floats); 68*4 bytes is 16B-multiple

__global__ __launch_bounds__(256) void attn_kernel()
{
    extern __shared__ float sm[];
    float* Qs  = sm;                 // 64*128
    float* Kst = Qs  + 64 * 128;     // 128*64 (Kst[d][c])
    float* Vs  = Kst + 128 * 64;     // 64*128
    float* Ps  = Vs  + 64 * 128;     // 64*PS

    const int tid = threadIdx.x;
    const int tx  = tid & 15;
    const int ty  = tid >> 4;
    const int qb  = blockIdx.x;      // query block (64 rows)
    const int h   = blockIdx.y;
    const int kvh = h >> 2;          // N_REP = 4

    // Load Q tile (already RoPE'd and pre-scaled by 1/sqrt(HD))
    for (int f = tid; f < 64 * 32; f += 256) {
        int r = f >> 5, c = (f & 31) << 2;
        *(float4*)&Qs[r * 128 + c] =
            *(const float4*)&g_Q[((size_t)(qb * 64 + r)) * DIM + h * HD + c];
    }

    float m[4], l[4], acc[4][8];
    #pragma unroll
    for (int a = 0; a < 4; a++) {
        m[a] = -1e30f; l[a] = 0.f;
        #pragma unroll
        for (int j = 0; j < 8; j++) acc[a][j] = 0.f;
    }

    const int kc  = tid >> 2;          // K loader: column (key index) 0..63
    const int kd0 = (tid & 3) << 5;    // K loader: d start 0/32/64/96

    for (int j = 0; j <= qb; j++) {
        __syncthreads();   // protect smem from previous iteration's readers

        // K tile, stored transposed Kst[d][c]
        {
            const float* kg = g_K + ((size_t)(j * 64 + kc)) * KVDIM + kvh * HD + kd0;
            #pragma unroll
            for (int q = 0; q < 8; q++) {
                float4 v = *(const float4*)(kg + q * 4);
                int d = kd0 + q * 4;
                Kst[(d + 0) * 64 + kc] = v.x;
                Kst[(d + 1) * 64 + kc] = v.y;
                Kst[(d + 2) * 64 + kc] = v.z;
                Kst[(d + 3) * 64 + kc] = v.w;
            }
        }
        // V tile
        for (int f = tid; f < 64 * 32; f += 256) {
            int r = f >> 5, c = (f & 31) << 2;
            *(float4*)&Vs[r * 128 + c] =
                *(const float4*)&g_V[((size_t)(j * 64 + r)) * KVDIM + kvh * HD + c];
        }
        __syncthreads();

        // S = Q @ K^T (64x64), each thread 4x4
        float s[4][4];
        #pragma unroll
        for (int a = 0; a < 4; a++)
            #pragma unroll
            for (int b = 0; b < 4; b++) s[a][b] = 0.f;

        for (int d = 0; d < 128; d += 4) {
            float4 k0 = *(float4*)&Kst[(d + 0) * 64 + tx * 4];
            float4 k1 = *(float4*)&Kst[(d + 1) * 64 + tx * 4];
            float4 k2 = *(float4*)&Kst[(d + 2) * 64 + tx * 4];
            float4 k3 = *(float4*)&Kst[(d + 3) * 64 + tx * 4];
            #pragma unroll
            for (int a = 0; a < 4; a++) {
                float4 q4 = *(float4*)&Qs[(ty * 4 + a) * 128 + d];
                s[a][0] += q4.x * k0.x + q4.y * k1.x + q4.z * k2.x + q4.w * k3.x;
                s[a][1] += q4.x * k0.y + q4.y * k1.y + q4.z * k2.y + q4.w * k3.y;
                s[a][2] += q4.x * k0.z + q4.y * k1.z + q4.z * k2.z + q4.w * k3.z;
                s[a][3] += q4.x * k0.w + q4.y * k1.w + q4.z * k2.w + q4.w * k3.w;
            }
        }

        // causal mask inside the diagonal block
        if (j == qb) {
            #pragma unroll
            for (int a = 0; a < 4; a++) {
                int qr = ty * 4 + a;
                #pragma unroll
                for (int b = 0; b < 4; b++)
                    if (tx * 4 + b > qr) s[a][b] = -1e30f;
            }
        }

        // online softmax update; row r = 4*ty+a spans the 16 tx lanes
        #pragma unroll
        for (int a = 0; a < 4; a++) {
            float rm = fmaxf(fmaxf(s[a][0], s[a][1]), fmaxf(s[a][2], s[a][3]));
            #pragma unroll
            for (int o = 8; o > 0; o >>= 1)
                rm = fmaxf(rm, __shfl_xor_sync(0xffffffffu, rm, o));
            float mn   = fmaxf(m[a], rm);
            float corr = __expf(m[a] - mn);
            float p0 = __expf(s[a][0] - mn);
            float p1 = __expf(s[a][1] - mn);
            float p2 = __expf(s[a][2] - mn);
            float p3 = __expf(s[a][3] - mn);
            float ps = p0 + p1 + p2 + p3;
            #pragma unroll
            for (int o = 8; o > 0; o >>= 1)
                ps += __shfl_xor_sync(0xffffffffu, ps, o);
            l[a] = l[a] * corr + ps;
            m[a] = mn;
            #pragma unroll
            for (int jj = 0; jj < 8; jj++) acc[a][jj] *= corr;
            *(float4*)&Ps[(ty * 4 + a) * PS + tx * 4] = make_float4(p0, p1, p2, p3);
        }
        __syncthreads();

        // acc += P @ V
        for (int c = 0; c < 64; c += 4) {
            float4 pr[4];
            #pragma unroll
            for (int a = 0; a < 4; a++)
                pr[a] = *(float4*)&Ps[(ty * 4 + a) * PS + c];
            #pragma unroll
            for (int cc = 0; cc < 4; cc++) {
                float4 v0 = *(float4*)&Vs[(c + cc) * 128 + tx * 4];
                float4 v1 = *(float4*)&Vs[(c + cc) * 128 + 64 + tx * 4];
                #pragma unroll
                for (int a = 0; a < 4; a++) {
                    float p = (cc == 0) ? pr[a].x : (cc == 1) ? pr[a].y
                            : (cc == 2) ? pr[a].z : pr[a].w;
                    acc[a][0] += p * v0.x; acc[a][1] += p * v0.y;
                    acc[a][2] += p * v0.z; acc[a][3] += p * v0.w;
                    acc[a][4] += p * v1.x; acc[a][5] += p * v1.y;
                    acc[a][6] += p * v1.z; acc[a][7] += p * v1.w;
                }
            }
        }
    }

    // epilogue: normalize by l, write [2048][NH*HD]
    #pragma unroll
    for (int a = 0; a < 4; a++) {
        float inv = 1.0f / l[a];
        int row = qb * 64 + ty * 4 + a;
        float* o = g_attn + (size_t)row * DIM + h * HD;
        *(float4*)(o + tx * 4) =
            make_float4(acc[a][0] * inv, acc[a][1] * inv, acc[a][2] * inv, acc[a][3] * inv);
        *(float4*)(o + 64 + tx * 4) =
            make_float4(acc[a][4] * inv, acc[a][5] * inv, acc[a][6] * inv, acc[a][7] * inv);
    }
}

#define ATT_SMEM ((64 * 128 * 3 + 64 * PS) * (int)sizeof(float))  // 115712 B

// ============================================================================
// kernel_launch: QKV GEMMs -> RoPE -> attention -> output GEMM.
// All launches on the default stream (graph-capturable; no allocs, no syncs).
// ============================================================================
extern "C" void kernel_launch(void* const* d_in, const int* in_sizes, int n_in,
                              void* d_out, int out_size)
{
    const float* x  = (const float*)d_in[0];
    const float* wq = (const float*)d_in[1];
    const float* wk = (const float*)d_in[2];
    const float* wv = (const float*)d_in[3];
    const float* wo = (const float*)d_in[4];
    float* out = (float*)d_out;

    float *Q, *K, *V, *ATT;
    cudaGetSymbolAddress((void**)&Q,   g_Q);
    cudaGetSymbolAddress((void**)&K,   g_K);
    cudaGetSymbolAddress((void**)&V,   g_V);
    cudaGetSymbolAddress((void**)&ATT, g_attn);

    dim3 blk(256);

    // QKV projections
    gemm_f32<<<dim3(DIM   / 128, SEQ / 128), blk>>>(x, wq, Q, SEQ, DIM,   DIM);
    gemm_f32<<<dim3(KVDIM / 128, SEQ / 128), blk>>>(x, wk, K, SEQ, KVDIM, DIM);
    gemm_f32<<<dim3(KVDIM / 128, SEQ / 128), blk>>>(x, wv, V, SEQ, KVDIM, DIM);

    // RoPE (fold 1/sqrt(HD) into Q)
    const float scale = 0.08838834764831845f;  // 1/sqrt(128)
    int nq = SEQ * NH  * (HD / 2);
    int nk = SEQ * NKV * (HD / 2);
    rope_kernel<<<(nq + 255) / 256, 256>>>(Q, NH,  scale);
    rope_kernel<<<(nk + 255) / 256, 256>>>(K, NKV, 1.0f);

    // Attention
    cudaFuncSetAttribute(attn_kernel,
                         cudaFuncAttributeMaxDynamicSharedMemorySize, ATT_SMEM);
    attn_kernel<<<dim3(SEQ / 64, NH), blk, ATT_SMEM>>>();

    // Output projection
    gemm_f32<<<dim3(DIM / 128, SEQ / 128), blk>>>(ATT, wo, out, SEQ, DIM, DIM);
}

// round 8
// speedup vs baseline: 1.8136x; 1.8136x over previous
#include <cuda_runtime.h>
#include <cuda_bf16.h>
#include <math.h>

// Problem constants
#define SEQ   2048
#define DIM   4096
#define NH    32
#define NKV   8
#define HD    128
#define KVDIM (NKV * HD)   // 1024

typedef unsigned int u32;

// -------- fp32 scratch --------
__device__ float g_Q[SEQ * DIM];
__device__ float g_K[SEQ * KVDIM];
__device__ float g_V[SEQ * KVDIM];
__device__ float g_attn[SEQ * DIM];

// -------- bf16 split operands (hi + lo residual) --------
__device__ __nv_bfloat16 g_xh[SEQ * DIM],    g_xl[SEQ * DIM];
__device__ __nv_bfloat16 g_wqh[DIM * DIM],   g_wql[DIM * DIM];     // transposed [N][K]
__device__ __nv_bfloat16 g_wkh[KVDIM * DIM], g_wkl[KVDIM * DIM];
__device__ __nv_bfloat16 g_wvh[KVDIM * DIM], g_wvl[KVDIM * DIM];
__device__ __nv_bfloat16 g_woh[DIM * DIM],   g_wol[DIM * DIM];
__device__ __nv_bfloat16 g_ah[SEQ * DIM],    g_al[SEQ * DIM];

// ============================================================================
// Split fp32 -> bf16 hi + bf16 lo(residual). Vectorized x4.
// ============================================================================
__global__ void split_kernel(const float* __restrict__ in,
                             __nv_bfloat16* __restrict__ hi,
                             __nv_bfloat16* __restrict__ lo, int n4)
{
    int i = blockIdx.x * blockDim.x + threadIdx.x;
    if (i >= n4) return;
    float4 v = ((const float4*)in)[i];
    __nv_bfloat162 h01, h23, l01, l23;
    h01.x = __float2bfloat16(v.x); h01.y = __float2bfloat16(v.y);
    h23.x = __float2bfloat16(v.z); h23.y = __float2bfloat16(v.w);
    l01.x = __float2bfloat16(v.x - __bfloat162float(h01.x));
    l01.y = __float2bfloat16(v.y - __bfloat162float(h01.y));
    l23.x = __float2bfloat16(v.z - __bfloat162float(h23.x));
    l23.y = __float2bfloat16(v.w - __bfloat162float(h23.y));
    ((__nv_bfloat162*)hi)[2 * i]     = h01;
    ((__nv_bfloat162*)hi)[2 * i + 1] = h23;
    ((__nv_bfloat162*)lo)[2 * i]     = l01;
    ((__nv_bfloat162*)lo)[2 * i + 1] = l23;
}

// ============================================================================
// Transpose + split: in fp32 [K][N] -> hi/lo bf16 [N][K].
// ============================================================================
__global__ void transpose_split_kernel(const float* __restrict__ in,
                                       __nv_bfloat16* __restrict__ hi,
                                       __nv_bfloat16* __restrict__ lo,
                                       int K, int N)
{
    __shared__ float t[32][33];
    int n0 = blockIdx.x * 32, k0 = blockIdx.y * 32;
    int tx = threadIdx.x, ty = threadIdx.y;   // (32, 8)
    #pragma unroll
    for (int i = 0; i < 4; i++)
        t[ty + i * 8][tx] = in[(size_t)(k0 + ty + i * 8) * N + n0 + tx];
    __syncthreads();
    #pragma unroll
    for (int i = 0; i < 4; i++) {
        float v = t[tx][ty + i * 8];
        __nv_bfloat16 h = __float2bfloat16(v);
        size_t o = (size_t)(n0 + ty + i * 8) * K + k0 + tx;
        hi[o] = h;
        lo[o] = __float2bfloat16(v - __bfloat162float(h));
    }
}

// ============================================================================
// bf16x3-split tensor-core GEMM: C[M,N] fp32 = A @ B^T
//   A: hi/lo bf16 [M][K] row-major;  B: hi/lo bf16 [N][K] row-major (K-major)
// 128x128x32 tiles, 256 threads (8 warps, 4m x 2n), mma.sync.m16n8k16,
// cp.async double-buffered smem, ldmatrix (non-trans) for both operands.
// ============================================================================
#define GBM   128
#define GBN   128
#define GBK   32
#define GLD   40                 // padded row stride in bf16 (conflict-free ldmatrix)
#define GTILE (GBM * GLD)        // bf16 elems per tile buffer
#define GTILEB (GTILE * 2)       // bytes
#define GSMEM (8 * GTILEB)       // 4 matrices x 2 stages = 81920 B

__device__ __forceinline__ void ldsm4(u32* r, u32 addr) {
    asm volatile("ldmatrix.sync.aligned.m8n8.x4.shared.b16 {%0,%1,%2,%3}, [%4];\n"
        : "=r"(r[0]), "=r"(r[1]), "=r"(r[2]), "=r"(r[3]) : "r"(addr));
}
__device__ __forceinline__ void mma16816(float* c, const u32* a, const u32* b) {
    asm volatile("mma.sync.aligned.m16n8k16.row.col.f32.bf16.bf16.f32 "
        "{%0,%1,%2,%3}, {%4,%5,%6,%7}, {%8,%9}, {%0,%1,%2,%3};\n"
        : "+f"(c[0]), "+f"(c[1]), "+f"(c[2]), "+f"(c[3])
        : "r"(a[0]), "r"(a[1]), "r"(a[2]), "r"(a[3]), "r"(b[0]), "r"(b[1]));
}
__device__ __forceinline__ void cp16(u32 dst, const void* src) {
    asm volatile("cp.async.cg.shared.global [%0], [%1], 16;\n" :: "r"(dst), "l"(src));
}

__global__ __launch_bounds__(256) void gemm_bf16x3(
    const __nv_bfloat16* __restrict__ Ah, const __nv_bfloat16* __restrict__ Al,
    const __nv_bfloat16* __restrict__ Bh, const __nv_bfloat16* __restrict__ Bl,
    float* __restrict__ C, int M, int N, int K)
{
    extern __shared__ __nv_bfloat16 smg[];
    __nv_bfloat16* sAh = smg;
    __nv_bfloat16* sAl = sAh + 2 * GTILE;
    __nv_bfloat16* sBh = sAl + 2 * GTILE;
    __nv_bfloat16* sBl = sBh + 2 * GTILE;

    const int tid  = threadIdx.x;
    const int lane = tid & 31;
    const int warp = tid >> 5;
    const int wm   = warp & 3;    // 0..3 -> 32-row slab
    const int wn   = warp >> 2;   // 0..1 -> 64-col slab
    const int m0   = blockIdx.y * GBM;
    const int n0   = blockIdx.x * GBN;

    const u32 sAh0 = (u32)__cvta_generic_to_shared(sAh);
    const u32 sAl0 = (u32)__cvta_generic_to_shared(sAl);
    const u32 sBh0 = (u32)__cvta_generic_to_shared(sBh);
    const u32 sBl0 = (u32)__cvta_generic_to_shared(sBl);

    // global->smem loader: 512 16B-chunks per tile, 2 per thread (rows r, r+64)
    const int lrow = tid >> 2;            // 0..63
    const int lkc  = (tid & 3) * 8;       // bf16 col 0,8,16,24
    const size_t gA = (size_t)(m0 + lrow) * K + lkc;
    const size_t gB = (size_t)(n0 + lrow) * K + lkc;
    const u32 sOff  = (u32)(lrow * GLD + lkc) * 2;
    const u32 sOff2 = sOff + 64 * GLD * 2;

    float acc[2][8][4];
    #pragma unroll
    for (int a = 0; a < 2; a++)
        #pragma unroll
        for (int b = 0; b < 8; b++)
            #pragma unroll
            for (int c = 0; c < 4; c++) acc[a][b][c] = 0.f;

    // ldmatrix fragment byte offsets within a stage
    const u32 aOff = (u32)((wm * 32 + (lane & 15)) * GLD + (lane >> 4) * 8) * 2;
    const u32 bOff = (u32)((wn * 64 + (lane & 7) + ((lane >> 4) & 1) * 8) * GLD
                           + ((lane >> 3) & 1) * 8) * 2;

    const int nk = K / GBK;

    // prologue: stage 0
    {
        cp16(sAh0 + sOff,  Ah + gA);  cp16(sAh0 + sOff2, Ah + gA + (size_t)64 * K);
        cp16(sAl0 + sOff,  Al + gA);  cp16(sAl0 + sOff2, Al + gA + (size_t)64 * K);
        cp16(sBh0 + sOff,  Bh + gB);  cp16(sBh0 + sOff2, Bh + gB + (size_t)64 * K);
        cp16(sBl0 + sOff,  Bl + gB);  cp16(sBl0 + sOff2, Bl + gB + (size_t)64 * K);
        asm volatile("cp.async.commit_group;\n");
    }

    for (int it = 0; it < nk; it++) {
        if (it + 1 < nk) {
            const int kk = (it + 1) * GBK;
            const u32 sb = (u32)(((it + 1) & 1) * GTILEB);
            cp16(sAh0 + sb + sOff,  Ah + gA + kk);
            cp16(sAh0 + sb + sOff2, Ah + gA + kk + (size_t)64 * K);
            cp16(sAl0 + sb + sOff,  Al + gA + kk);
            cp16(sAl0 + sb + sOff2, Al + gA + kk + (size_t)64 * K);
            cp16(sBh0 + sb + sOff,  Bh + gB + kk);
            cp16(sBh0 + sb + sOff2, Bh + gB + kk + (size_t)64 * K);
            cp16(sBl0 + sb + sOff,  Bl + gB + kk);
            cp16(sBl0 + sb + sOff2, Bl + gB + kk + (size_t)64 * K);
            asm volatile("cp.async.commit_group;\n");
            asm volatile("cp.async.wait_group 1;\n");
        } else {
            asm volatile("cp.async.wait_group 0;\n");
        }
        __syncthreads();

        const u32 sb = (u32)((it & 1) * GTILEB);
        #pragma unroll
        for (int ks = 0; ks < 2; ks++) {
            const u32 kb = sb + ks * 32;    // k16 step = 32 bytes
            u32 a_hi[2][4], a_lo[2][4], b_hi[4][4], b_lo[4][4];
            #pragma unroll
            for (int mt = 0; mt < 2; mt++) {
                ldsm4(a_hi[mt], sAh0 + kb + aOff + mt * (16 * GLD * 2));
                ldsm4(a_lo[mt], sAl0 + kb + aOff + mt * (16 * GLD * 2));
            }
            #pragma unroll
            for (int np = 0; np < 4; np++) {
                ldsm4(b_hi[np], sBh0 + kb + bOff + np * (16 * GLD * 2));
                ldsm4(b_lo[np], sBl0 + kb + bOff + np * (16 * GLD * 2));
            }
            #pragma unroll
            for (int mt = 0; mt < 2; mt++)
                #pragma unroll
                for (int nt = 0; nt < 8; nt++) {
                    const u32* bh = &b_hi[nt >> 1][(nt & 1) * 2];
                    const u32* bl = &b_lo[nt >> 1][(nt & 1) * 2];
                    mma16816(acc[mt][nt], a_hi[mt], bh);
                    mma16816(acc[mt][nt], a_lo[mt], bh);
                    mma16816(acc[mt][nt], a_hi[mt], bl);
                }
        }
        __syncthreads();
    }

    // epilogue: fragment -> fp32 global
    const int erow = m0 + wm * 32 + (lane >> 2);
    const int ecol = n0 + wn * 64 + (lane & 3) * 2;
    #pragma unroll
    for (int mt = 0; mt < 2; mt++)
        #pragma unroll
        for (int nt = 0; nt < 8; nt++) {
            int r = erow + mt * 16;
            int c = ecol + nt * 8;
            *(float2*)&C[(size_t)r * N + c] =
                make_float2(acc[mt][nt][0], acc[mt][nt][1]);
            *(float2*)&C[(size_t)(r + 8) * N + c] =
                make_float2(acc[mt][nt][2], acc[mt][nt][3]);
        }
}

// ============================================================================
// RoPE (interleaved pairs), optional scale folded in.
// ============================================================================
__global__ void rope_kernel(float* __restrict__ t, int n_heads, float scale)
{
    int idx = blockIdx.x * blockDim.x + threadIdx.x;
    int total = SEQ * n_heads * (HD / 2);
    if (idx >= total) return;
    int i   = idx & 63;
    int h   = (idx >> 6) % n_heads;
    int pos = idx / (64 * n_heads);

    float inv = powf(10000.0f, -(float)(2 * i) / 128.0f);
    float ang = (float)pos * inv;
    float s, c;
    sincosf(ang, &s, &c);

    float* p = t + ((size_t)pos * n_heads + h) * HD + 2 * i;
    float a = p[0], b = p[1];
    p[0] = (a * c - b * s) * scale;
    p[1] = (a * s + b * c) * scale;
}

// ============================================================================
// Flash-style causal GQA attention, fp32 (unchanged from R7-passing version).
// ============================================================================
#define PS 68

__global__ __launch_bounds__(256) void attn_kernel()
{
    extern __shared__ float sm[];
    float* Qs  = sm;
    float* Kst = Qs  + 64 * 128;
    float* Vs  = Kst + 128 * 64;
    float* Ps  = Vs  + 64 * 128;

    const int tid = threadIdx.x;
    const int tx  = tid & 15;
    const int ty  = tid >> 4;
    const int qb  = blockIdx.x;
    const int h   = blockIdx.y;
    const int kvh = h >> 2;

    for (int f = tid; f < 64 * 32; f += 256) {
        int r = f >> 5, c = (f & 31) << 2;
        *(float4*)&Qs[r * 128 + c] =
            *(const float4*)&g_Q[((size_t)(qb * 64 + r)) * DIM + h * HD + c];
    }

    float m[4], l[4], acc[4][8];
    #pragma unroll
    for (int a = 0; a < 4; a++) {
        m[a] = -1e30f; l[a] = 0.f;
        #pragma unroll
        for (int j = 0; j < 8; j++) acc[a][j] = 0.f;
    }

    const int kc  = tid >> 2;
    const int kd0 = (tid & 3) << 5;

    for (int j = 0; j <= qb; j++) {
        __syncthreads();
        {
            const float* kg = g_K + ((size_t)(j * 64 + kc)) * KVDIM + kvh * HD + kd0;
            #pragma unroll
            for (int q = 0; q < 8; q++) {
                float4 v = *(const float4*)(kg + q * 4);
                int d = kd0 + q * 4;
                Kst[(d + 0) * 64 + kc] = v.x;
                Kst[(d + 1) * 64 + kc] = v.y;
                Kst[(d + 2) * 64 + kc] = v.z;
                Kst[(d + 3) * 64 + kc] = v.w;
            }
        }
        for (int f = tid; f < 64 * 32; f += 256) {
            int r = f >> 5, c = (f & 31) << 2;
            *(float4*)&Vs[r * 128 + c] =
                *(const float4*)&g_V[((size_t)(j * 64 + r)) * KVDIM + kvh * HD + c];
        }
        __syncthreads();

        float s[4][4];
        #pragma unroll
        for (int a = 0; a < 4; a++)
            #pragma unroll
            for (int b = 0; b < 4; b++) s[a][b] = 0.f;

        for (int d = 0; d < 128; d += 4) {
            float4 k0 = *(float4*)&Kst[(d + 0) * 64 + tx * 4];
            float4 k1 = *(float4*)&Kst[(d + 1) * 64 + tx * 4];
            float4 k2 = *(float4*)&Kst[(d + 2) * 64 + tx * 4];
            float4 k3 = *(float4*)&Kst[(d + 3) * 64 + tx * 4];
            #pragma unroll
            for (int a = 0; a < 4; a++) {
                float4 q4 = *(float4*)&Qs[(ty * 4 + a) * 128 + d];
                s[a][0] += q4.x * k0.x + q4.y * k1.x + q4.z * k2.x + q4.w * k3.x;
                s[a][1] += q4.x * k0.y + q4.y * k1.y + q4.z * k2.y + q4.w * k3.y;
                s[a][2] += q4.x * k0.z + q4.y * k1.z + q4.z * k2.z + q4.w * k3.z;
                s[a][3] += q4.x * k0.w + q4.y * k1.w + q4.z * k2.w + q4.w * k3.w;
            }
        }

        if (j == qb) {
            #pragma unroll
            for (int a = 0; a < 4; a++) {
                int qr = ty * 4 + a;
                #pragma unroll
                for (int b = 0; b < 4; b++)
                    if (tx * 4 + b > qr) s[a][b] = -1e30f;
            }
        }

        #pragma unroll
        for (int a = 0; a < 4; a++) {
            float rm = fmaxf(fmaxf(s[a][0], s[a][1]), fmaxf(s[a][2], s[a][3]));
            #pragma unroll
            for (int o = 8; o > 0; o >>= 1)
                rm = fmaxf(rm, __shfl_xor_sync(0xffffffffu, rm, o));
            float mn   = fmaxf(m[a], rm);
            float corr = __expf(m[a] - mn);
            float p0 = __expf(s[a][0] - mn);
            float p1 = __expf(s[a][1] - mn);
            float p2 = __expf(s[a][2] - mn);
            float p3 = __expf(s[a][3] - mn);
            float ps = p0 + p1 + p2 + p3;
            #pragma unroll
            for (int o = 8; o > 0; o >>= 1)
                ps += __shfl_xor_sync(0xffffffffu, ps, o);
            l[a] = l[a] * corr + ps;
            m[a] = mn;
            #pragma unroll
            for (int jj = 0; jj < 8; jj++) acc[a][jj] *= corr;
            *(float4*)&Ps[(ty * 4 + a) * PS + tx * 4] = make_float4(p0, p1, p2, p3);
        }
        __syncthreads();

        for (int c = 0; c < 64; c += 4) {
            float4 pr[4];
            #pragma unroll
            for (int a = 0; a < 4; a++)
                pr[a] = *(float4*)&Ps[(ty * 4 + a) * PS + c];
            #pragma unroll
            for (int cc = 0; cc < 4; cc++) {
                float4 v0 = *(float4*)&Vs[(c + cc) * 128 + tx * 4];
                float4 v1 = *(float4*)&Vs[(c + cc) * 128 + 64 + tx * 4];
                #pragma unroll
                for (int a = 0; a < 4; a++) {
                    float p = (cc == 0) ? pr[a].x : (cc == 1) ? pr[a].y
                            : (cc == 2) ? pr[a].z : pr[a].w;
                    acc[a][0] += p * v0.x; acc[a][1] += p * v0.y;
                    acc[a][2] += p * v0.z; acc[a][3] += p * v0.w;
                    acc[a][4] += p * v1.x; acc[a][5] += p * v1.y;
                    acc[a][6] += p * v1.z; acc[a][7] += p * v1.w;
                }
            }
        }
    }

    #pragma unroll
    for (int a = 0; a < 4; a++) {
        float inv = 1.0f / l[a];
        int row = qb * 64 + ty * 4 + a;
        float* o = g_attn + (size_t)row * DIM + h * HD;
        *(float4*)(o + tx * 4) =
            make_float4(acc[a][0] * inv, acc[a][1] * inv, acc[a][2] * inv, acc[a][3] * inv);
        *(float4*)(o + 64 + tx * 4) =
            make_float4(acc[a][4] * inv, acc[a][5] * inv, acc[a][6] * inv, acc[a][7] * inv);
    }
}

#define ATT_SMEM ((64 * 128 * 3 + 64 * PS) * (int)sizeof(float))

// ============================================================================
// kernel_launch
// ============================================================================
extern "C" void kernel_launch(void* const* d_in, const int* in_sizes, int n_in,
                              void* d_out, int out_size)
{
    const float* x  = (const float*)d_in[0];
    const float* wq = (const float*)d_in[1];
    const float* wk = (const float*)d_in[2];
    const float* wv = (const float*)d_in[3];
    const float* wo = (const float*)d_in[4];
    float* out = (float*)d_out;

    float *Q, *K, *V, *ATT;
    cudaGetSymbolAddress((void**)&Q,   g_Q);
    cudaGetSymbolAddress((void**)&K,   g_K);
    cudaGetSymbolAddress((void**)&V,   g_V);
    cudaGetSymbolAddress((void**)&ATT, g_attn);

    __nv_bfloat16 *xh, *xl, *wqh, *wql, *wkh, *wkl, *wvh, *wvl, *woh, *wol, *ah, *al;
    cudaGetSymbolAddress((void**)&xh,  g_xh);  cudaGetSymbolAddress((void**)&xl,  g_xl);
    cudaGetSymbolAddress((void**)&wqh, g_wqh); cudaGetSymbolAddress((void**)&wql, g_wql);
    cudaGetSymbolAddress((void**)&wkh, g_wkh); cudaGetSymbolAddress((void**)&wkl, g_wkl);
    cudaGetSymbolAddress((void**)&wvh, g_wvh); cudaGetSymbolAddress((void**)&wvl, g_wvl);
    cudaGetSymbolAddress((void**)&woh, g_woh); cudaGetSymbolAddress((void**)&wol, g_wol);
    cudaGetSymbolAddress((void**)&ah,  g_ah);  cudaGetSymbolAddress((void**)&al,  g_al);

    cudaFuncSetAttribute(gemm_bf16x3,
                         cudaFuncAttributeMaxDynamicSharedMemorySize, GSMEM);
    cudaFuncSetAttribute(attn_kernel,
                         cudaFuncAttributeMaxDynamicSharedMemorySize, ATT_SMEM);

    // 1) split x; transpose+split weights
    split_kernel<<<(SEQ * DIM / 4 + 255) / 256, 256>>>(x, xh, xl, SEQ * DIM / 4);
    transpose_split_kernel<<<dim3(DIM   / 32, DIM / 32), dim3(32, 8)>>>(wq, wqh, wql, DIM, DIM);
    transpose_split_kernel<<<dim3(KVDIM / 32, DIM / 32), dim3(32, 8)>>>(wk, wkh, wkl, DIM, KVDIM);
    transpose_split_kernel<<<dim3(KVDIM / 32, DIM / 32), dim3(32, 8)>>>(wv, wvh, wvl, DIM, KVDIM);
    transpose_split_kernel<<<dim3(DIM   / 32, DIM / 32), dim3(32, 8)>>>(wo, woh, wol, DIM, DIM);

    // 2) QKV projections (tensor cores)
    gemm_bf16x3<<<dim3(DIM   / GBN, SEQ / GBM), 256, GSMEM>>>(xh, xl, wqh, wql, Q, SEQ, DIM,   DIM);
    gemm_bf16x3<<<dim3(KVDIM / GBN, SEQ / GBM), 256, GSMEM>>>(xh, xl, wkh, wkl, K, SEQ, KVDIM, DIM);
    gemm_bf16x3<<<dim3(KVDIM / GBN, SEQ / GBM), 256, GSMEM>>>(xh, xl, wvh, wvl, V, SEQ, KVDIM, DIM);

    // 3) RoPE (fold 1/sqrt(HD) into Q)
    const float scale = 0.08838834764831845f;
    int nq = SEQ * NH  * (HD / 2);
    int nk = SEQ * NKV * (HD / 2);
    rope_kernel<<<(nq + 255) / 256, 256>>>(Q, NH,  scale);
    rope_kernel<<<(nk + 255) / 256, 256>>>(K, NKV, 1.0f);

    // 4) attention
    attn_kernel<<<dim3(SEQ / 64, NH), 256, ATT_SMEM>>>();

    // 5) output projection
    split_kernel<<<(SEQ * DIM / 4 + 255) / 256, 256>>>(ATT, ah, al, SEQ * DIM / 4);
    gemm_bf16x3<<<dim3(DIM / GBN, SEQ / GBM), 256, GSMEM>>>(ah, al, woh, wol, out, SEQ, DIM, DIM);
}